// round 7
// baseline (speedup 1.0000x reference)
#include <cuda_runtime.h>
#include <math.h>

#define NB 32
#define NP 24564
#define NT 20
#define NC 81
#define TOT (NB * NP)
#define TOT2 (TOT / 2)

#define MCHUNKS 8
#define MCHUNK ((NP + MCHUNKS - 1) / MCHUNKS)        // 3071
#define MWARPS (NB * NT * MCHUNKS)                   // 5120 warps
#define MBLOCKS (MWARPS / 8)                         // 640 blocks

// ---------------- device scratch (explicit zero-init; no allocations) ----------------
__device__ unsigned long long g_keys[NB * NT] = {};  // packed (ov_bits<<32)|~p per (b,t)
__device__ signed char        g_conf[TOT];           // conf_t per row: -1 / 0 / cls
__device__ double g_accL = 0.0, g_accC = 0.0, g_accN = 0.0;
__device__ unsigned int g_ticket = 0;

// ---------------- warp-per-(b,t,chunk) argmax over priors ----------------
__global__ void __launch_bounds__(256) k_match(const float* __restrict__ priors,
                                               const float* __restrict__ targets) {
    const int lane  = threadIdx.x & 31;
    const int gwarp = blockIdx.x * 8 + (threadIdx.x >> 5);   // 0..MWARPS-1
    const int chunk = gwarp & (MCHUNKS - 1);
    const int bt    = gwarp >> 3;                            // 0..639
    const int t     = bt % NT;
    const int b     = bt / NT;

    const float* tg = targets + (size_t)(b * NT + t) * 5;
    const float tx0 = tg[0], ty0 = tg[1], tx1 = tg[2], ty1 = tg[3];
    const float ta  = (tx1 - tx0) * (ty1 - ty0);

    const int pend = min(NP, (chunk + 1) * MCHUNK);
    float bestOv = 0.0f;
    int   bestP  = 0;

    for (int p = chunk * MCHUNK + lane; p < pend; p += 32) {
        const float4 pr = reinterpret_cast<const float4*>(priors)[p];
        const float hz = 0.5f * pr.z, hw = 0.5f * pr.w;
        const float iw = fmaxf(fminf(tx1, pr.x + hz) - fmaxf(tx0, pr.x - hz), 0.0f);
        const float ih = fmaxf(fminf(ty1, pr.y + hw) - fmaxf(ty0, pr.y - hw), 0.0f);
        const float inter = iw * ih;
        const float ov = __fdividef(inter, ta + pr.z * pr.w - inter);
        if (ov > bestOv) { bestOv = ov; bestP = p; }        // keeps smallest p in-lane
    }

    unsigned long long key = ((unsigned long long)__float_as_uint(bestOv) << 32) |
                             (unsigned int)(~(unsigned int)bestP);
    #pragma unroll
    for (int o = 16; o; o >>= 1) {
        unsigned long long other = __shfl_xor_sync(0xffffffffu, key, o);
        key = (other > key) ? other : key;
    }
    if (lane == 0) atomicMax(&g_keys[b * NT + t], key);
}

// ---------------- thread-per-row: match decode + conf_t + smooth-L1 ----------------
__device__ __forceinline__ float sl1f(float d) {
    float a = fabsf(d);
    return (a < 1.0f) ? 0.5f * d * d : a - 0.5f;
}

__global__ void __launch_bounds__(256) k_decode(const float* __restrict__ loc,
                                                const float* __restrict__ priors,
                                                const float* __restrict__ targets) {
    __shared__ float s_x0[NB * NT], s_y0[NB * NT], s_x1[NB * NT],
                     s_y1[NB * NT], s_ta[NB * NT], s_lb[NB * NT];
    __shared__ int    s_bp[NB * NT];
    __shared__ double sL[8], sN[8];

    for (int i = threadIdx.x; i < NB * NT; i += blockDim.x) {
        const float* tg = targets + (size_t)i * 5;
        float x0 = tg[0], y0 = tg[1], x1 = tg[2], y1 = tg[3];
        s_x0[i] = x0; s_y0[i] = y0; s_x1[i] = x1; s_y1[i] = y1;
        s_ta[i] = (x1 - x0) * (y1 - y0);
        s_lb[i] = tg[4];
        s_bp[i] = (int)(~(unsigned int)(g_keys[i] & 0xffffffffull));
    }
    __syncthreads();

    const int row = blockIdx.x * 256 + threadIdx.x;
    double myL = 0.0, myN = 0.0;

    if (row < TOT) {
        const int b = row / NP;
        const int p = row - b * NP;
        const int base = b * NT;

        const float4 pr = reinterpret_cast<const float4*>(priors)[p];
        const float px0 = pr.x - 0.5f * pr.z, py0 = pr.y - 0.5f * pr.w;
        const float px1 = pr.x + 0.5f * pr.z, py1 = pr.y + 0.5f * pr.w;
        const float parea = pr.z * pr.w;

        float bestOv = -1.0f;
        int bestT = 0, forcedT = -1;
        #pragma unroll
        for (int t = 0; t < NT; t++) {
            const int i = base + t;
            float iw = fmaxf(fminf(s_x1[i], px1) - fmaxf(s_x0[i], px0), 0.0f);
            float ih = fmaxf(fminf(s_y1[i], py1) - fmaxf(s_y0[i], py0), 0.0f);
            float inter = iw * ih;
            float ov = __fdividef(inter, s_ta[i] + parea - inter);
            if (ov > bestOv) { bestOv = ov; bestT = t; }   // tie -> smallest t
            if (s_bp[i] == p) forcedT = t;                 // ascending -> largest t wins
        }
        if (forcedT >= 0) { bestOv = 2.0f; bestT = forcedT; }

        const int ti = base + bestT;
        int cls = (int)s_lb[ti] + 1;
        if (bestOv < 0.5f) cls = -1;
        if (bestOv < 0.4f) cls = 0;
        g_conf[row] = (signed char)cls;

        if (cls > 0) {
            const float4 ld = reinterpret_cast<const float4*>(loc)[row];
            const float mx0 = s_x0[ti], my0 = s_y0[ti];
            const float mx1 = s_x1[ti], my1 = s_y1[ti];
            const float gx = ((mx0 + mx1) * 0.5f - pr.x) / (0.1f * pr.z);
            const float gy = ((my0 + my1) * 0.5f - pr.y) / (0.1f * pr.w);
            const float gw2 = __logf((mx1 - mx0) / pr.z) * 5.0f;   // /0.2
            const float gh2 = __logf((my1 - my0) / pr.w) * 5.0f;
            myL = (double)(sl1f(ld.x - gx) + sl1f(ld.y - gy) +
                           sl1f(ld.z - gw2) + sl1f(ld.w - gh2));
            myN = 1.0;
        }
    }

    #pragma unroll
    for (int o = 16; o; o >>= 1) {
        myL += __shfl_down_sync(0xffffffffu, myL, o);
        myN += __shfl_down_sync(0xffffffffu, myN, o);
    }
    const int lane = threadIdx.x & 31, w = threadIdx.x >> 5;
    if (lane == 0) { sL[w] = myL; sN[w] = myN; }
    __syncthreads();
    if (threadIdx.x == 0) {
        double tL = 0.0, tN = 0.0;
        #pragma unroll
        for (int i = 0; i < 8; i++) { tL += sL[i]; tN += sN[i]; }
        if (tL != 0.0 || tN != 0.0) { atomicAdd(&g_accL, tL); atomicAdd(&g_accN, tN); }
    }
}

// ---------------- half-warp-per-row streaming focal loss + finalize ----------------
// Unshifted logsumexp (logits ~N(0,1) -> fp32-safe). 16-lane half owns one row;
// lane hl==0 re-loads the target logit directly (L1/L2 hit) -- no select chain.
#define FOCAL_BLOCKS 2048
__global__ void __launch_bounds__(256) k_focal(const float* __restrict__ conf,
                                               float* __restrict__ out) {
    __shared__ double sC[8];

    const int lane = threadIdx.x & 31;
    const int hl   = lane & 15;           // lane within half-warp
    const int h    = lane >> 4;           // which half (row parity)
    const int wInB = threadIdx.x >> 5;
    const int gw   = blockIdx.x * 8 + wInB;
    const int nW   = FOCAL_BLOCKS * 8;

    // block 0: reset g_keys for the next graph replay (already consumed by k_decode)
    if (blockIdx.x == 0) {
        for (int i = threadIdx.x; i < NB * NT; i += 256) g_keys[i] = 0ull;
    }

    const float* rowp = conf + (size_t)(2 * gw + h) * NC;   // this half's row base
    const signed char* cp = g_conf + (2 * gw + h);
    const size_t cstride = (size_t)nW * 2 * NC;
    const int    pstride = nW * 2;

    float aC = 0.0f;

    for (int r2 = gw; r2 < TOT2; r2 += nW, rowp += cstride, cp += pstride) {
        const int cls = (int)(*cp);                       // uniform within half
        const float* cr = rowp + hl;

        const float c0 = __ldcs(cr);
        const float c1 = __ldcs(cr + 16);
        const float c2 = __ldcs(cr + 32);
        const float c3 = __ldcs(cr + 48);
        const float c4 = __ldcs(cr + 64);
        float e5 = 0.0f;
        if (hl == 0) e5 = __expf(__ldcs(cr + 80));        // element 80

        float e = __expf(c0) + __expf(c1) + __expf(c2) +
                  __expf(c3) + __expf(c4) + e5;
        #pragma unroll
        for (int o = 8; o; o >>= 1) e += __shfl_xor_sync(0xffffffffu, e, o);

        if (hl == 0) {                                    // lanes 0 and 16 only
            const int tgt = (cls > 0) ? cls : 0;
            const float lv = rowp[tgt];                   // direct re-load (cache hit)
            const float logpt = lv - __logf(e);
            const float pt    = __expf(logpt);
            const float at    = (cls > 0) ? 0.25f : 0.75f;
            const float om    = 1.0f - pt;
            aC += (cls >= 0) ? (-at * om * om * logpt) : 0.0f;
        }
    }

    // reduce per-lane float partials: warp -> block -> global
    #pragma unroll
    for (int o = 16; o; o >>= 1) aC += __shfl_xor_sync(0xffffffffu, aC, o);
    if (lane == 0) sC[wInB] = (double)aC;
    __syncthreads();
    if (threadIdx.x == 0) {
        double t = 0.0;
        #pragma unroll
        for (int i = 0; i < 8; i++) t += sC[i];
        atomicAdd(&g_accC, t);
        __threadfence();
        const unsigned my = atomicAdd(&g_ticket, 1u);
        if (my == FOCAL_BLOCKS - 1) {                      // last block finalizes
            const double L = *(volatile double*)&g_accL;
            const double C = *(volatile double*)&g_accC;
            const double N = *(volatile double*)&g_accN;
            out[0] = (float)(L / N);
            out[1] = (float)(C / N);
            *(volatile double*)&g_accL = 0.0;              // reset for next replay
            *(volatile double*)&g_accC = 0.0;
            *(volatile double*)&g_accN = 0.0;
            *(volatile unsigned int*)&g_ticket = 0u;
        }
    }
}

// ---------------- launch ----------------
extern "C" void kernel_launch(void* const* d_in, const int* in_sizes, int n_in,
                              void* d_out, int out_size) {
    const float* loc     = (const float*)d_in[0];
    const float* conf    = (const float*)d_in[1];
    const float* priors  = (const float*)d_in[2];
    const float* targets = (const float*)d_in[3];
    float* out = (float*)d_out;

    k_match<<<MBLOCKS, 256>>>(priors, targets);
    k_decode<<<(TOT + 255) / 256, 256>>>(loc, priors, targets);
    k_focal<<<FOCAL_BLOCKS, 256>>>(conf, out);
}

// round 8
// speedup vs baseline: 1.1548x; 1.1548x over previous
#include <cuda_runtime.h>
#include <math.h>

#define NB 32
#define NP 24564
#define NT 20
#define NC 81
#define TOT (NB * NP)
#define TOT2 (TOT / 2)

#define MCHUNKS 32
#define MCHUNK ((NP + MCHUNKS - 1) / MCHUNKS)        // 768
#define MWARPS (NB * NT * MCHUNKS)                   // 20480 warps
#define MBLOCKS (MWARPS / 8)                         // 2560 blocks

// ---------------- device scratch (explicit zero-init; no allocations) ----------------
__device__ unsigned long long g_keys[NB * NT] = {};  // packed (ov_bits<<32)|~p per (b,t)
__device__ signed char        g_conf[TOT];           // conf_t per row: -1 / 0 / cls
__device__ double g_accL = 0.0, g_accC = 0.0, g_accN = 0.0;
__device__ unsigned int g_ticket = 0;

// ---------------- warp-per-(b,t,chunk) argmax over priors ----------------
__global__ void __launch_bounds__(256) k_match(const float* __restrict__ priors,
                                               const float* __restrict__ targets) {
    const int lane  = threadIdx.x & 31;
    const int gwarp = blockIdx.x * 8 + (threadIdx.x >> 5);   // 0..MWARPS-1
    const int chunk = gwarp & (MCHUNKS - 1);
    const int bt    = gwarp >> 5;                            // 0..639
    const int t     = bt % NT;
    const int b     = bt / NT;

    const float* tg = targets + (size_t)(b * NT + t) * 5;
    const float tx0 = tg[0], ty0 = tg[1], tx1 = tg[2], ty1 = tg[3];
    const float ta  = (tx1 - tx0) * (ty1 - ty0);

    const int pend = min(NP, (chunk + 1) * MCHUNK);
    float bestOv = 0.0f;
    int   bestP  = 0;

    #pragma unroll 4
    for (int p = chunk * MCHUNK + lane; p < pend; p += 32) {
        const float4 pr = reinterpret_cast<const float4*>(priors)[p];
        const float hz = 0.5f * pr.z, hw = 0.5f * pr.w;
        const float iw = fmaxf(fminf(tx1, pr.x + hz) - fmaxf(tx0, pr.x - hz), 0.0f);
        const float ih = fmaxf(fminf(ty1, pr.y + hw) - fmaxf(ty0, pr.y - hw), 0.0f);
        const float inter = iw * ih;
        const float ov = __fdividef(inter, ta + pr.z * pr.w - inter);
        if (ov > bestOv) { bestOv = ov; bestP = p; }        // keeps smallest p in-lane
    }

    unsigned long long key = ((unsigned long long)__float_as_uint(bestOv) << 32) |
                             (unsigned int)(~(unsigned int)bestP);
    #pragma unroll
    for (int o = 16; o; o >>= 1) {
        unsigned long long other = __shfl_xor_sync(0xffffffffu, key, o);
        key = (other > key) ? other : key;
    }
    if (lane == 0) atomicMax(&g_keys[b * NT + t], key);
}

// ---------------- thread-per-row: match decode + conf_t + smooth-L1 ----------------
__device__ __forceinline__ float sl1f(float d) {
    float a = fabsf(d);
    return (a < 1.0f) ? 0.5f * d * d : a - 0.5f;
}

__global__ void __launch_bounds__(256) k_decode(const float* __restrict__ loc,
                                                const float* __restrict__ priors,
                                                const float* __restrict__ targets) {
    __shared__ float s_x0[NB * NT], s_y0[NB * NT], s_x1[NB * NT],
                     s_y1[NB * NT], s_ta[NB * NT], s_lb[NB * NT];
    __shared__ int    s_bp[NB * NT];
    __shared__ double sL[8], sN[8];

    for (int i = threadIdx.x; i < NB * NT; i += blockDim.x) {
        const float* tg = targets + (size_t)i * 5;
        float x0 = tg[0], y0 = tg[1], x1 = tg[2], y1 = tg[3];
        s_x0[i] = x0; s_y0[i] = y0; s_x1[i] = x1; s_y1[i] = y1;
        s_ta[i] = (x1 - x0) * (y1 - y0);
        s_lb[i] = tg[4];
        s_bp[i] = (int)(~(unsigned int)(g_keys[i] & 0xffffffffull));
    }
    __syncthreads();

    const int row = blockIdx.x * 256 + threadIdx.x;
    double myL = 0.0, myN = 0.0;

    if (row < TOT) {
        const int b = row / NP;
        const int p = row - b * NP;
        const int base = b * NT;

        const float4 pr = reinterpret_cast<const float4*>(priors)[p];
        const float px0 = pr.x - 0.5f * pr.z, py0 = pr.y - 0.5f * pr.w;
        const float px1 = pr.x + 0.5f * pr.z, py1 = pr.y + 0.5f * pr.w;
        const float parea = pr.z * pr.w;

        float bestOv = -1.0f;
        int bestT = 0, forcedT = -1;
        #pragma unroll
        for (int t = 0; t < NT; t++) {
            const int i = base + t;
            float iw = fmaxf(fminf(s_x1[i], px1) - fmaxf(s_x0[i], px0), 0.0f);
            float ih = fmaxf(fminf(s_y1[i], py1) - fmaxf(s_y0[i], py0), 0.0f);
            float inter = iw * ih;
            float ov = __fdividef(inter, s_ta[i] + parea - inter);
            if (ov > bestOv) { bestOv = ov; bestT = t; }   // tie -> smallest t
            if (s_bp[i] == p) forcedT = t;                 // ascending -> largest t wins
        }
        if (forcedT >= 0) { bestOv = 2.0f; bestT = forcedT; }

        const int ti = base + bestT;
        int cls = (int)s_lb[ti] + 1;
        if (bestOv < 0.5f) cls = -1;
        if (bestOv < 0.4f) cls = 0;
        g_conf[row] = (signed char)cls;

        if (cls > 0) {
            const float4 ld = reinterpret_cast<const float4*>(loc)[row];
            const float mx0 = s_x0[ti], my0 = s_y0[ti];
            const float mx1 = s_x1[ti], my1 = s_y1[ti];
            const float gx = ((mx0 + mx1) * 0.5f - pr.x) / (0.1f * pr.z);
            const float gy = ((my0 + my1) * 0.5f - pr.y) / (0.1f * pr.w);
            const float gw2 = __logf((mx1 - mx0) / pr.z) * 5.0f;   // /0.2
            const float gh2 = __logf((my1 - my0) / pr.w) * 5.0f;
            myL = (double)(sl1f(ld.x - gx) + sl1f(ld.y - gy) +
                           sl1f(ld.z - gw2) + sl1f(ld.w - gh2));
            myN = 1.0;
        }
    }

    #pragma unroll
    for (int o = 16; o; o >>= 1) {
        myL += __shfl_down_sync(0xffffffffu, myL, o);
        myN += __shfl_down_sync(0xffffffffu, myN, o);
    }
    const int lane = threadIdx.x & 31, w = threadIdx.x >> 5;
    if (lane == 0) { sL[w] = myL; sN[w] = myN; }
    __syncthreads();
    if (threadIdx.x == 0) {
        double tL = 0.0, tN = 0.0;
        #pragma unroll
        for (int i = 0; i < 8; i++) { tL += sL[i]; tN += sN[i]; }
        if (tL != 0.0 || tN != 0.0) { atomicAdd(&g_accL, tL); atomicAdd(&g_accN, tN); }
    }
}

// ---------------- half-warp-per-row streaming focal loss + finalize ----------------
// Unshifted logsumexp (logits ~N(0,1) -> fp32-safe). 16-lane half owns one row;
// 2 row-pairs (4 rows) per loop iteration, loads front-batched for MLP.
#define FOCAL_BLOCKS 2048
__global__ void __launch_bounds__(256) k_focal(const float* __restrict__ conf,
                                               float* __restrict__ out) {
    __shared__ double sC[8];

    const int lane = threadIdx.x & 31;
    const int hl   = lane & 15;           // lane within half-warp
    const int h    = lane >> 4;           // which half (row parity)
    const int wInB = threadIdx.x >> 5;
    const int gw   = blockIdx.x * 8 + wInB;
    const int nW   = FOCAL_BLOCKS * 8;    // 16384

    // block 0: reset g_keys for the next graph replay (already consumed by k_decode)
    if (blockIdx.x == 0) {
        for (int i = threadIdx.x; i < NB * NT; i += 256) g_keys[i] = 0ull;
    }

    const size_t rstride = (size_t)nW * 2 * NC;     // floats per r2 step of nW
    const float* rpA = conf + (size_t)(2 * gw + h) * NC;
    const signed char* cpA = g_conf + (2 * gw + h);

    float aC = 0.0f;
    int r2 = gw;

    // main: two row-pairs per iteration
    for (; r2 + nW < TOT2; r2 += 2 * nW, rpA += 2 * rstride, cpA += 4 * nW) {
        const float* rpB = rpA + rstride;
        const signed char* cpB = cpA + 2 * nW;
        const int clsA = (int)(*cpA);
        const int clsB = (int)(*cpB);
        const float* crA = rpA + hl;
        const float* crB = rpB + hl;

        const float a0 = __ldcs(crA),      b0 = __ldcs(crB);
        const float a1 = __ldcs(crA + 16), b1 = __ldcs(crB + 16);
        const float a2 = __ldcs(crA + 32), b2 = __ldcs(crB + 32);
        const float a3 = __ldcs(crA + 48), b3 = __ldcs(crB + 48);
        const float a4 = __ldcs(crA + 64), b4 = __ldcs(crB + 64);
        const float a5 = (hl == 0) ? __ldcs(crA + 80) : -INFINITY;
        const float b5 = (hl == 0) ? __ldcs(crB + 80) : -INFINITY;

        float eA = __expf(a0) + __expf(a1) + __expf(a2) +
                   __expf(a3) + __expf(a4) + __expf(a5);
        float eB = __expf(b0) + __expf(b1) + __expf(b2) +
                   __expf(b3) + __expf(b4) + __expf(b5);
        #pragma unroll
        for (int o = 8; o; o >>= 1) {
            eA += __shfl_xor_sync(0xffffffffu, eA, o);
            eB += __shfl_xor_sync(0xffffffffu, eB, o);
        }

        if (hl == 0) {                                    // lanes 0 and 16 only
            const int tA = (clsA > 0) ? clsA : 0;
            const int tB = (clsB > 0) ? clsB : 0;
            const float lvA = rpA[tA];                    // cache-hit re-load
            const float lvB = rpB[tB];
            const float lpA = lvA - __logf(eA);
            const float lpB = lvB - __logf(eB);
            const float ptA = __expf(lpA), ptB = __expf(lpB);
            const float atA = (clsA > 0) ? 0.25f : 0.75f;
            const float atB = (clsB > 0) ? 0.25f : 0.75f;
            const float oA = 1.0f - ptA, oB = 1.0f - ptB;
            aC += (clsA >= 0) ? (-atA * oA * oA * lpA) : 0.0f;
            aC += (clsB >= 0) ? (-atB * oB * oB * lpB) : 0.0f;
        }
    }

    // epilogue: single row-pair
    for (; r2 < TOT2; r2 += nW, rpA += rstride, cpA += 2 * nW) {
        const int cls = (int)(*cpA);
        const float* cr = rpA + hl;
        const float c0 = __ldcs(cr);
        const float c1 = __ldcs(cr + 16);
        const float c2 = __ldcs(cr + 32);
        const float c3 = __ldcs(cr + 48);
        const float c4 = __ldcs(cr + 64);
        const float c5 = (hl == 0) ? __ldcs(cr + 80) : -INFINITY;

        float e = __expf(c0) + __expf(c1) + __expf(c2) +
                  __expf(c3) + __expf(c4) + __expf(c5);
        #pragma unroll
        for (int o = 8; o; o >>= 1) e += __shfl_xor_sync(0xffffffffu, e, o);

        if (hl == 0) {
            const int tgt = (cls > 0) ? cls : 0;
            const float lv = rpA[tgt];
            const float logpt = lv - __logf(e);
            const float pt    = __expf(logpt);
            const float at    = (cls > 0) ? 0.25f : 0.75f;
            const float om    = 1.0f - pt;
            aC += (cls >= 0) ? (-at * om * om * logpt) : 0.0f;
        }
    }

    // reduce per-lane float partials: warp -> block -> global
    #pragma unroll
    for (int o = 16; o; o >>= 1) aC += __shfl_xor_sync(0xffffffffu, aC, o);
    if (lane == 0) sC[wInB] = (double)aC;
    __syncthreads();
    if (threadIdx.x == 0) {
        double t = 0.0;
        #pragma unroll
        for (int i = 0; i < 8; i++) t += sC[i];
        atomicAdd(&g_accC, t);
        __threadfence();
        const unsigned my = atomicAdd(&g_ticket, 1u);
        if (my == FOCAL_BLOCKS - 1) {                      // last block finalizes
            const double L = *(volatile double*)&g_accL;
            const double C = *(volatile double*)&g_accC;
            const double N = *(volatile double*)&g_accN;
            out[0] = (float)(L / N);
            out[1] = (float)(C / N);
            *(volatile double*)&g_accL = 0.0;              // reset for next replay
            *(volatile double*)&g_accC = 0.0;
            *(volatile double*)&g_accN = 0.0;
            *(volatile unsigned int*)&g_ticket = 0u;
        }
    }
}

// ---------------- launch ----------------
extern "C" void kernel_launch(void* const* d_in, const int* in_sizes, int n_in,
                              void* d_out, int out_size) {
    const float* loc     = (const float*)d_in[0];
    const float* conf    = (const float*)d_in[1];
    const float* priors  = (const float*)d_in[2];
    const float* targets = (const float*)d_in[3];
    float* out = (float*)d_out;

    k_match<<<MBLOCKS, 256>>>(priors, targets);
    k_decode<<<(TOT + 255) / 256, 256>>>(loc, priors, targets);
    k_focal<<<FOCAL_BLOCKS, 256>>>(conf, out);
}

// round 9
// speedup vs baseline: 1.1815x; 1.0231x over previous
#include <cuda_runtime.h>
#include <math.h>

#define NB 32
#define NP 24564
#define NT 20
#define NC 81
#define TOT (NB * NP)
#define TOT2 (TOT / 2)

#define TG 4                                  // truths per warp in k_match
#define NTG (NT / TG)                         // 5 truth groups
#define MCHUNKS 64
#define MCHUNK ((NP + MCHUNKS - 1) / MCHUNKS) // 384
#define MWARPS (NB * NTG * MCHUNKS)           // 10240 warps
#define MBLOCKS (MWARPS / 8)                  // 1280 blocks

// ---------------- device scratch (explicit zero-init; no allocations) ----------------
__device__ unsigned long long g_keys[NB * NT] = {};  // packed (ov_bits<<32)|~p per (b,t)
__device__ signed char        g_conf[TOT];           // conf_t per row: -1 / 0 / cls
__device__ double g_accL = 0.0, g_accC = 0.0, g_accN = 0.0;
__device__ unsigned int g_ticket = 0;

// ---------------- warp-per-(b,tgroup,chunk) argmax over priors ----------------
// One prior load + point-form serves 4 truths -> ~16 slots per (prior,truth).
__global__ void __launch_bounds__(256) k_match(const float* __restrict__ priors,
                                               const float* __restrict__ targets) {
    const int lane  = threadIdx.x & 31;
    const int gwarp = blockIdx.x * 8 + (threadIdx.x >> 5);   // 0..MWARPS-1
    const int chunk = gwarp & (MCHUNKS - 1);
    const int btg   = gwarp / MCHUNKS;                       // 0..NB*NTG-1
    const int tg    = btg % NTG;
    const int b     = btg / NTG;

    // load 4 truth boxes (uniform across warp)
    float tx0[TG], ty0[TG], tx1[TG], ty1[TG], ta[TG];
    const float* tbase = targets + (size_t)(b * NT + tg * TG) * 5;
    #pragma unroll
    for (int j = 0; j < TG; j++) {
        tx0[j] = tbase[j * 5 + 0]; ty0[j] = tbase[j * 5 + 1];
        tx1[j] = tbase[j * 5 + 2]; ty1[j] = tbase[j * 5 + 3];
        ta[j]  = (tx1[j] - tx0[j]) * (ty1[j] - ty0[j]);
    }

    const int pend = min(NP, (chunk + 1) * MCHUNK);
    float bestOv[TG];
    int   bestP[TG];
    #pragma unroll
    for (int j = 0; j < TG; j++) { bestOv[j] = 0.0f; bestP[j] = 0; }

    #pragma unroll 4
    for (int p = chunk * MCHUNK + lane; p < pend; p += 32) {
        const float4 pr = reinterpret_cast<const float4*>(priors)[p];
        const float hz = 0.5f * pr.z, hw = 0.5f * pr.w;
        const float px0 = pr.x - hz, px1 = pr.x + hz;
        const float py0 = pr.y - hw, py1 = pr.y + hw;
        const float pa  = pr.z * pr.w;
        #pragma unroll
        for (int j = 0; j < TG; j++) {
            const float iw = fmaxf(fminf(tx1[j], px1) - fmaxf(tx0[j], px0), 0.0f);
            const float ih = fmaxf(fminf(ty1[j], py1) - fmaxf(ty0[j], py0), 0.0f);
            const float inter = iw * ih;
            const float ov = __fdividef(inter, ta[j] + pa - inter);
            if (ov > bestOv[j]) { bestOv[j] = ov; bestP[j] = p; }  // smallest p in-lane
        }
    }

    #pragma unroll
    for (int j = 0; j < TG; j++) {
        unsigned long long key = ((unsigned long long)__float_as_uint(bestOv[j]) << 32) |
                                 (unsigned int)(~(unsigned int)bestP[j]);
        #pragma unroll
        for (int o = 16; o; o >>= 1) {
            unsigned long long other = __shfl_xor_sync(0xffffffffu, key, o);
            key = (other > key) ? other : key;
        }
        if (lane == 0) atomicMax(&g_keys[b * NT + tg * TG + j], key);
    }
}

// ---------------- thread-per-row: match decode + conf_t + smooth-L1 ----------------
__device__ __forceinline__ float sl1f(float d) {
    float a = fabsf(d);
    return (a < 1.0f) ? 0.5f * d * d : a - 0.5f;
}

__global__ void __launch_bounds__(256) k_decode(const float* __restrict__ loc,
                                                const float* __restrict__ priors,
                                                const float* __restrict__ targets) {
    __shared__ float4 s_box[NB * NT];    // x0, y0, x1, y1
    __shared__ float4 s_meta[NB * NT];   // ta, label, bp-bits, unused
    __shared__ double sL[8], sN[8];

    for (int i = threadIdx.x; i < NB * NT; i += blockDim.x) {
        const float* tg = targets + (size_t)i * 5;
        const float x0 = tg[0], y0 = tg[1], x1 = tg[2], y1 = tg[3];
        s_box[i] = make_float4(x0, y0, x1, y1);
        const int bp = (int)(~(unsigned int)(g_keys[i] & 0xffffffffull));
        s_meta[i] = make_float4((x1 - x0) * (y1 - y0), tg[4], __int_as_float(bp), 0.0f);
    }
    __syncthreads();

    const int row = blockIdx.x * 256 + threadIdx.x;
    double myL = 0.0, myN = 0.0;

    if (row < TOT) {
        const int b = row / NP;
        const int p = row - b * NP;
        const int base = b * NT;

        const float4 pr = reinterpret_cast<const float4*>(priors)[p];
        const float px0 = pr.x - 0.5f * pr.z, py0 = pr.y - 0.5f * pr.w;
        const float px1 = pr.x + 0.5f * pr.z, py1 = pr.y + 0.5f * pr.w;
        const float parea = pr.z * pr.w;

        float bestOv = -1.0f;
        int bestT = 0, forcedT = -1;
        #pragma unroll
        for (int t = 0; t < NT; t++) {
            const float4 bx = s_box[base + t];
            const float4 mt = s_meta[base + t];
            float iw = fmaxf(fminf(bx.z, px1) - fmaxf(bx.x, px0), 0.0f);
            float ih = fmaxf(fminf(bx.w, py1) - fmaxf(bx.y, py0), 0.0f);
            float inter = iw * ih;
            float ov = __fdividef(inter, mt.x + parea - inter);
            if (ov > bestOv) { bestOv = ov; bestT = t; }   // tie -> smallest t
            if (__float_as_int(mt.z) == p) forcedT = t;    // ascending -> largest t wins
        }
        if (forcedT >= 0) { bestOv = 2.0f; bestT = forcedT; }

        const int ti = base + bestT;
        const float4 mbox = s_box[ti];
        const float4 mmet = s_meta[ti];
        int cls = (int)mmet.y + 1;
        if (bestOv < 0.5f) cls = -1;
        if (bestOv < 0.4f) cls = 0;
        g_conf[row] = (signed char)cls;

        if (cls > 0) {
            const float4 ld = reinterpret_cast<const float4*>(loc)[row];
            const float gx = ((mbox.x + mbox.z) * 0.5f - pr.x) / (0.1f * pr.z);
            const float gy = ((mbox.y + mbox.w) * 0.5f - pr.y) / (0.1f * pr.w);
            const float gw2 = __logf((mbox.z - mbox.x) / pr.z) * 5.0f;  // /0.2
            const float gh2 = __logf((mbox.w - mbox.y) / pr.w) * 5.0f;
            myL = (double)(sl1f(ld.x - gx) + sl1f(ld.y - gy) +
                           sl1f(ld.z - gw2) + sl1f(ld.w - gh2));
            myN = 1.0;
        }
    }

    #pragma unroll
    for (int o = 16; o; o >>= 1) {
        myL += __shfl_down_sync(0xffffffffu, myL, o);
        myN += __shfl_down_sync(0xffffffffu, myN, o);
    }
    const int lane = threadIdx.x & 31, w = threadIdx.x >> 5;
    if (lane == 0) { sL[w] = myL; sN[w] = myN; }
    __syncthreads();
    if (threadIdx.x == 0) {
        double tL = 0.0, tN = 0.0;
        #pragma unroll
        for (int i = 0; i < 8; i++) { tL += sL[i]; tN += sN[i]; }
        if (tL != 0.0 || tN != 0.0) { atomicAdd(&g_accL, tL); atomicAdd(&g_accN, tN); }
    }
}

// ---------------- half-warp-per-row streaming focal loss + finalize ----------------
// Unshifted logsumexp (logits ~N(0,1) -> fp32-safe). 16-lane half owns one row;
// 2 row-pairs (4 rows) per loop iteration, loads front-batched for MLP.
#define FOCAL_BLOCKS 2048
__global__ void __launch_bounds__(256) k_focal(const float* __restrict__ conf,
                                               float* __restrict__ out) {
    __shared__ double sC[8];

    const int lane = threadIdx.x & 31;
    const int hl   = lane & 15;           // lane within half-warp
    const int h    = lane >> 4;           // which half (row parity)
    const int wInB = threadIdx.x >> 5;
    const int gw   = blockIdx.x * 8 + wInB;
    const int nW   = FOCAL_BLOCKS * 8;    // 16384

    // block 0: reset g_keys for the next graph replay (already consumed by k_decode)
    if (blockIdx.x == 0) {
        for (int i = threadIdx.x; i < NB * NT; i += 256) g_keys[i] = 0ull;
    }

    const size_t rstride = (size_t)nW * 2 * NC;     // floats per r2 step of nW
    const float* rpA = conf + (size_t)(2 * gw + h) * NC;
    const signed char* cpA = g_conf + (2 * gw + h);

    float aC = 0.0f;
    int r2 = gw;

    // main: two row-pairs per iteration
    for (; r2 + nW < TOT2; r2 += 2 * nW, rpA += 2 * rstride, cpA += 4 * nW) {
        const float* rpB = rpA + rstride;
        const signed char* cpB = cpA + 2 * nW;
        const int clsA = (int)(*cpA);
        const int clsB = (int)(*cpB);
        const float* crA = rpA + hl;
        const float* crB = rpB + hl;

        const float a0 = __ldcs(crA),      b0 = __ldcs(crB);
        const float a1 = __ldcs(crA + 16), b1 = __ldcs(crB + 16);
        const float a2 = __ldcs(crA + 32), b2 = __ldcs(crB + 32);
        const float a3 = __ldcs(crA + 48), b3 = __ldcs(crB + 48);
        const float a4 = __ldcs(crA + 64), b4 = __ldcs(crB + 64);
        const float a5 = (hl == 0) ? __ldcs(crA + 80) : -INFINITY;
        const float b5 = (hl == 0) ? __ldcs(crB + 80) : -INFINITY;

        float eA = __expf(a0) + __expf(a1) + __expf(a2) +
                   __expf(a3) + __expf(a4) + __expf(a5);
        float eB = __expf(b0) + __expf(b1) + __expf(b2) +
                   __expf(b3) + __expf(b4) + __expf(b5);
        #pragma unroll
        for (int o = 8; o; o >>= 1) {
            eA += __shfl_xor_sync(0xffffffffu, eA, o);
            eB += __shfl_xor_sync(0xffffffffu, eB, o);
        }

        if (hl == 0) {                                    // lanes 0 and 16 only
            const int tA = (clsA > 0) ? clsA : 0;
            const int tB = (clsB > 0) ? clsB : 0;
            const float lvA = rpA[tA];                    // cache-hit re-load
            const float lvB = rpB[tB];
            const float lpA = lvA - __logf(eA);
            const float lpB = lvB - __logf(eB);
            const float ptA = __expf(lpA), ptB = __expf(lpB);
            const float atA = (clsA > 0) ? 0.25f : 0.75f;
            const float atB = (clsB > 0) ? 0.25f : 0.75f;
            const float oA = 1.0f - ptA, oB = 1.0f - ptB;
            aC += (clsA >= 0) ? (-atA * oA * oA * lpA) : 0.0f;
            aC += (clsB >= 0) ? (-atB * oB * oB * lpB) : 0.0f;
        }
    }

    // epilogue: single row-pair
    for (; r2 < TOT2; r2 += nW, rpA += rstride, cpA += 2 * nW) {
        const int cls = (int)(*cpA);
        const float* cr = rpA + hl;
        const float c0 = __ldcs(cr);
        const float c1 = __ldcs(cr + 16);
        const float c2 = __ldcs(cr + 32);
        const float c3 = __ldcs(cr + 48);
        const float c4 = __ldcs(cr + 64);
        const float c5 = (hl == 0) ? __ldcs(cr + 80) : -INFINITY;

        float e = __expf(c0) + __expf(c1) + __expf(c2) +
                  __expf(c3) + __expf(c4) + __expf(c5);
        #pragma unroll
        for (int o = 8; o; o >>= 1) e += __shfl_xor_sync(0xffffffffu, e, o);

        if (hl == 0) {
            const int tgt = (cls > 0) ? cls : 0;
            const float lv = rpA[tgt];
            const float logpt = lv - __logf(e);
            const float pt    = __expf(logpt);
            const float at    = (cls > 0) ? 0.25f : 0.75f;
            const float om    = 1.0f - pt;
            aC += (cls >= 0) ? (-at * om * om * logpt) : 0.0f;
        }
    }

    // reduce per-lane float partials: warp -> block -> global
    #pragma unroll
    for (int o = 16; o; o >>= 1) aC += __shfl_xor_sync(0xffffffffu, aC, o);
    if (lane == 0) sC[wInB] = (double)aC;
    __syncthreads();
    if (threadIdx.x == 0) {
        double t = 0.0;
        #pragma unroll
        for (int i = 0; i < 8; i++) t += sC[i];
        atomicAdd(&g_accC, t);
        __threadfence();
        const unsigned my = atomicAdd(&g_ticket, 1u);
        if (my == FOCAL_BLOCKS - 1) {                      // last block finalizes
            const double L = *(volatile double*)&g_accL;
            const double C = *(volatile double*)&g_accC;
            const double N = *(volatile double*)&g_accN;
            out[0] = (float)(L / N);
            out[1] = (float)(C / N);
            *(volatile double*)&g_accL = 0.0;              // reset for next replay
            *(volatile double*)&g_accC = 0.0;
            *(volatile double*)&g_accN = 0.0;
            *(volatile unsigned int*)&g_ticket = 0u;
        }
    }
}

// ---------------- launch ----------------
extern "C" void kernel_launch(void* const* d_in, const int* in_sizes, int n_in,
                              void* d_out, int out_size) {
    const float* loc     = (const float*)d_in[0];
    const float* conf    = (const float*)d_in[1];
    const float* priors  = (const float*)d_in[2];
    const float* targets = (const float*)d_in[3];
    float* out = (float*)d_out;

    k_match<<<MBLOCKS, 256>>>(priors, targets);
    k_decode<<<(TOT + 255) / 256, 256>>>(loc, priors, targets);
    k_focal<<<FOCAL_BLOCKS, 256>>>(conf, out);
}

// round 10
// speedup vs baseline: 1.1895x; 1.0068x over previous
#include <cuda_runtime.h>
#include <math.h>

#define NB 32
#define NP 24564
#define NT 20
#define NC 81
#define TOT (NB * NP)
#define TOT2 (TOT / 2)

// ---- k_stream partition: every 4th block does matching, rest do lse ----
#define TG 4                                  // truths per match-warp
#define NTG 5                                 // truth groups (NT/TG)
#define MCHUNKS 48
#define MCHUNK 512                            // 48*512 = 24576 >= NP
#define G1_TOT 3840
#define G1_MATCH (G1_TOT / 4)                 // 960 blocks -> 7680 warps = 32*5*48
#define G1_LSE (G1_TOT - G1_MATCH)            // 2880 blocks
#define NW_LSE (G1_LSE * 8)                   // 23040 warps

#define G2 ((TOT + 255) / 256)                // 3071 blocks

// ---------------- device scratch (explicit zero-init; no allocations) ----------------
__device__ unsigned long long g_keys[NB * NT] = {};  // packed (ov_bits<<32)|~p per (b,t)
__device__ float g_lse[TOT];                         // per-row sum(exp(logits))
__device__ double g_accL = 0.0, g_accC = 0.0, g_accN = 0.0;
__device__ unsigned int g_ticket = 0;

// =====================================================================
// Launch 1: fused [lse stream || prior-argmax matching], block-partitioned
// =====================================================================
__global__ void __launch_bounds__(256) k_stream(const float* __restrict__ conf,
                                                const float* __restrict__ priors,
                                                const float* __restrict__ targets) {
    const int bid  = blockIdx.x;
    const int lane = threadIdx.x & 31;

    if ((bid & 3) == 3) {
        // ---------------- MATCH PART (bid -> 0..959) ----------------
        const int mb    = bid >> 2;
        const int gwarp = mb * 8 + (threadIdx.x >> 5);       // 0..7679
        const int chunk = gwarp % MCHUNKS;
        const int btg   = gwarp / MCHUNKS;                   // 0..159
        const int tg    = btg % NTG;
        const int b     = btg / NTG;

        float tx0[TG], ty0[TG], tx1[TG], ty1[TG], ta[TG];
        const float* tbase = targets + (size_t)(b * NT + tg * TG) * 5;
        #pragma unroll
        for (int j = 0; j < TG; j++) {
            tx0[j] = tbase[j * 5 + 0]; ty0[j] = tbase[j * 5 + 1];
            tx1[j] = tbase[j * 5 + 2]; ty1[j] = tbase[j * 5 + 3];
            ta[j]  = (tx1[j] - tx0[j]) * (ty1[j] - ty0[j]);
        }

        const int pend = min(NP, (chunk + 1) * MCHUNK);
        float bestOv[TG];
        int   bestP[TG];
        #pragma unroll
        for (int j = 0; j < TG; j++) { bestOv[j] = 0.0f; bestP[j] = 0; }

        #pragma unroll 4
        for (int p = chunk * MCHUNK + lane; p < pend; p += 32) {
            const float4 pr = reinterpret_cast<const float4*>(priors)[p];
            const float hz = 0.5f * pr.z, hw = 0.5f * pr.w;
            const float px0 = pr.x - hz, px1 = pr.x + hz;
            const float py0 = pr.y - hw, py1 = pr.y + hw;
            const float pa  = pr.z * pr.w;
            #pragma unroll
            for (int j = 0; j < TG; j++) {
                const float iw = fmaxf(fminf(tx1[j], px1) - fmaxf(tx0[j], px0), 0.0f);
                const float ih = fmaxf(fminf(ty1[j], py1) - fmaxf(ty0[j], py0), 0.0f);
                const float inter = iw * ih;
                const float ov = __fdividef(inter, ta[j] + pa - inter);
                if (ov > bestOv[j]) { bestOv[j] = ov; bestP[j] = p; } // smallest p in-lane
            }
        }

        #pragma unroll
        for (int j = 0; j < TG; j++) {
            unsigned long long key =
                ((unsigned long long)__float_as_uint(bestOv[j]) << 32) |
                (unsigned int)(~(unsigned int)bestP[j]);
            #pragma unroll
            for (int o = 16; o; o >>= 1) {
                unsigned long long other = __shfl_xor_sync(0xffffffffu, key, o);
                key = (other > key) ? other : key;
            }
            if (lane == 0) atomicMax(&g_keys[b * NT + tg * TG + j], key);
        }
    } else {
        // ---------------- LSE PART (bid -> 0..2879) ----------------
        // Unshifted logsumexp (logits ~N(0,1) -> fp32-safe). 16-lane half owns
        // one row; 2 row-pairs per iteration; stores sum(exp) per row.
        const int lb   = bid - (bid >> 2);     // lse block index 0..G1_LSE-1
        const int hl   = lane & 15;
        const int h    = lane >> 4;
        const int gw   = lb * 8 + (threadIdx.x >> 5);
        const int nW   = NW_LSE;

        const size_t rstride = (size_t)nW * 2 * NC;
        const float* rpA = conf + (size_t)(2 * gw + h) * NC;

        int r2 = gw;
        for (; r2 + nW < TOT2; r2 += 2 * nW, rpA += 2 * rstride) {
            const float* rpB = rpA + rstride;
            const float* crA = rpA + hl;
            const float* crB = rpB + hl;

            const float a0 = __ldcs(crA),      b0 = __ldcs(crB);
            const float a1 = __ldcs(crA + 16), b1 = __ldcs(crB + 16);
            const float a2 = __ldcs(crA + 32), b2 = __ldcs(crB + 32);
            const float a3 = __ldcs(crA + 48), b3 = __ldcs(crB + 48);
            const float a4 = __ldcs(crA + 64), b4 = __ldcs(crB + 64);
            const float a5 = (hl == 0) ? __ldcs(crA + 80) : -INFINITY;
            const float b5 = (hl == 0) ? __ldcs(crB + 80) : -INFINITY;

            float eA = __expf(a0) + __expf(a1) + __expf(a2) +
                       __expf(a3) + __expf(a4) + __expf(a5);
            float eB = __expf(b0) + __expf(b1) + __expf(b2) +
                       __expf(b3) + __expf(b4) + __expf(b5);
            #pragma unroll
            for (int o = 8; o; o >>= 1) {
                eA += __shfl_xor_sync(0xffffffffu, eA, o);
                eB += __shfl_xor_sync(0xffffffffu, eB, o);
            }
            if (hl == 0) {                       // lanes 0 and 16
                g_lse[2 * r2 + h] = eA;
                g_lse[2 * (r2 + nW) + h] = eB;
            }
        }
        for (; r2 < TOT2; r2 += nW, rpA += rstride) {
            const float* cr = rpA + hl;
            const float c0 = __ldcs(cr);
            const float c1 = __ldcs(cr + 16);
            const float c2 = __ldcs(cr + 32);
            const float c3 = __ldcs(cr + 48);
            const float c4 = __ldcs(cr + 64);
            const float c5 = (hl == 0) ? __ldcs(cr + 80) : -INFINITY;
            float e = __expf(c0) + __expf(c1) + __expf(c2) +
                      __expf(c3) + __expf(c4) + __expf(c5);
            #pragma unroll
            for (int o = 8; o; o >>= 1) e += __shfl_xor_sync(0xffffffffu, e, o);
            if (hl == 0) g_lse[2 * r2 + h] = e;
        }
    }
}

// =====================================================================
// Launch 2: thread-per-row decode + smooth-L1 + focal tail + finalize
// =====================================================================
__device__ __forceinline__ float sl1f(float d) {
    float a = fabsf(d);
    return (a < 1.0f) ? 0.5f * d * d : a - 0.5f;
}

__global__ void __launch_bounds__(256) k_tail(const float* __restrict__ loc,
                                              const float* __restrict__ conf,
                                              const float* __restrict__ priors,
                                              const float* __restrict__ targets,
                                              float* __restrict__ out) {
    __shared__ float4 s_box[NB * NT];    // x0, y0, x1, y1
    __shared__ float4 s_meta[NB * NT];   // ta, label, bp-bits, unused
    __shared__ double sL[8], sC[8], sN[8];
    __shared__ int sLast;

    for (int i = threadIdx.x; i < NB * NT; i += blockDim.x) {
        const float* tg = targets + (size_t)i * 5;
        const float x0 = tg[0], y0 = tg[1], x1 = tg[2], y1 = tg[3];
        s_box[i] = make_float4(x0, y0, x1, y1);
        const int bp = (int)(~(unsigned int)(g_keys[i] & 0xffffffffull));
        s_meta[i] = make_float4((x1 - x0) * (y1 - y0), tg[4], __int_as_float(bp), 0.0f);
    }
    __syncthreads();

    const int row = blockIdx.x * 256 + threadIdx.x;
    double myL = 0.0, myC = 0.0, myN = 0.0;

    if (row < TOT) {
        const int b = row / NP;
        const int p = row - b * NP;
        const int base = b * NT;

        const float4 pr = reinterpret_cast<const float4*>(priors)[p];
        const float px0 = pr.x - 0.5f * pr.z, py0 = pr.y - 0.5f * pr.w;
        const float px1 = pr.x + 0.5f * pr.z, py1 = pr.y + 0.5f * pr.w;
        const float parea = pr.z * pr.w;

        float bestOv = -1.0f;
        int bestT = 0, forcedT = -1;
        #pragma unroll
        for (int t = 0; t < NT; t++) {
            const float4 bx = s_box[base + t];
            const float4 mt = s_meta[base + t];
            float iw = fmaxf(fminf(bx.z, px1) - fmaxf(bx.x, px0), 0.0f);
            float ih = fmaxf(fminf(bx.w, py1) - fmaxf(bx.y, py0), 0.0f);
            float inter = iw * ih;
            float ov = __fdividef(inter, mt.x + parea - inter);
            if (ov > bestOv) { bestOv = ov; bestT = t; }   // tie -> smallest t
            if (__float_as_int(mt.z) == p) forcedT = t;    // ascending -> largest t wins
        }
        if (forcedT >= 0) { bestOv = 2.0f; bestT = forcedT; }

        const int ti = base + bestT;
        const float4 mbox = s_box[ti];
        int cls = (int)s_meta[ti].y + 1;
        if (bestOv < 0.5f) cls = -1;
        if (bestOv < 0.4f) cls = 0;

        // focal tail: lse from scratch, target logit gathered (4B)
        const float e   = g_lse[row];
        const int   tgt = (cls > 0) ? cls : 0;
        const float lv  = __ldg(conf + (size_t)row * NC + tgt);
        const float logpt = lv - __logf(e);
        const float pt    = __expf(logpt);
        const float at    = (cls > 0) ? 0.25f : 0.75f;
        const float om    = 1.0f - pt;
        if (cls >= 0) myC = (double)(-at * om * om * logpt);

        if (cls > 0) {
            const float4 ld = reinterpret_cast<const float4*>(loc)[row];
            const float gx = ((mbox.x + mbox.z) * 0.5f - pr.x) / (0.1f * pr.z);
            const float gy = ((mbox.y + mbox.w) * 0.5f - pr.y) / (0.1f * pr.w);
            const float gw2 = __logf((mbox.z - mbox.x) / pr.z) * 5.0f;  // /0.2
            const float gh2 = __logf((mbox.w - mbox.y) / pr.w) * 5.0f;
            myL = (double)(sl1f(ld.x - gx) + sl1f(ld.y - gy) +
                           sl1f(ld.z - gw2) + sl1f(ld.w - gh2));
            myN = 1.0;
        }
    }

    #pragma unroll
    for (int o = 16; o; o >>= 1) {
        myL += __shfl_down_sync(0xffffffffu, myL, o);
        myC += __shfl_down_sync(0xffffffffu, myC, o);
        myN += __shfl_down_sync(0xffffffffu, myN, o);
    }
    const int lane = threadIdx.x & 31, w = threadIdx.x >> 5;
    if (lane == 0) { sL[w] = myL; sC[w] = myC; sN[w] = myN; }
    if (threadIdx.x == 0) sLast = 0;
    __syncthreads();

    if (threadIdx.x == 0) {
        double tL = 0.0, tC = 0.0, tN = 0.0;
        #pragma unroll
        for (int i = 0; i < 8; i++) { tL += sL[i]; tC += sC[i]; tN += sN[i]; }
        if (tL != 0.0 || tN != 0.0) { atomicAdd(&g_accL, tL); atomicAdd(&g_accN, tN); }
        atomicAdd(&g_accC, tC);
        __threadfence();
        const unsigned my = atomicAdd(&g_ticket, 1u);
        if (my == G2 - 1) sLast = 1;
    }
    __syncthreads();

    if (sLast) {
        // all other blocks fully done (ticket): safe to reset scratch for replay
        for (int i = threadIdx.x; i < NB * NT; i += 256) g_keys[i] = 0ull;
        if (threadIdx.x == 0) {
            const double L = *(volatile double*)&g_accL;
            const double C = *(volatile double*)&g_accC;
            const double N = *(volatile double*)&g_accN;
            out[0] = (float)(L / N);
            out[1] = (float)(C / N);
            *(volatile double*)&g_accL = 0.0;
            *(volatile double*)&g_accC = 0.0;
            *(volatile double*)&g_accN = 0.0;
            *(volatile unsigned int*)&g_ticket = 0u;
        }
    }
}

// ---------------- launch ----------------
extern "C" void kernel_launch(void* const* d_in, const int* in_sizes, int n_in,
                              void* d_out, int out_size) {
    const float* loc     = (const float*)d_in[0];
    const float* conf    = (const float*)d_in[1];
    const float* priors  = (const float*)d_in[2];
    const float* targets = (const float*)d_in[3];
    float* out = (float*)d_out;

    k_stream<<<G1_TOT, 256>>>(conf, priors, targets);
    k_tail<<<G2, 256>>>(loc, conf, priors, targets, out);
}

// round 11
// speedup vs baseline: 1.2020x; 1.0105x over previous
#include <cuda_runtime.h>
#include <math.h>

#define NB 32
#define NP 24564
#define NT 20
#define NC 81
#define TOT (NB * NP)
#define TOT2 (TOT / 2)

// ---- k_stream partition: every 4th block does matching, rest do lse ----
#define TG 4                                  // truths per match-warp
#define NTG 5                                 // truth groups (NT/TG)
#define MCHUNKS 48
#define MCHUNK 512                            // 48*512 = 24576 >= NP
#define G1_TOT 3840
#define G1_MATCH (G1_TOT / 4)                 // 960 blocks -> 7680 warps = 32*5*48
#define G1_LSE (G1_TOT - G1_MATCH)            // 2880 blocks
#define NW_LSE (G1_LSE * 8)                   // 23040 warps

#define G2 ((TOT + 255) / 256)                // 3071 blocks

// ---------------- device scratch (explicit zero-init; no allocations) ----------------
__device__ unsigned long long g_keys[NB * NT] = {};  // packed (ov_bits<<32)|~p per (b,t)
__device__ float2 g_lse2[TOT];                       // per-row {sum(exp), logit[0]}
__device__ double g_accL = 0.0, g_accC = 0.0, g_accN = 0.0;
__device__ unsigned int g_ticket = 0;

// =====================================================================
// Launch 1: fused [lse stream || prior-argmax matching], block-partitioned
// =====================================================================
__global__ void __launch_bounds__(256) k_stream(const float* __restrict__ conf,
                                                const float* __restrict__ priors,
                                                const float* __restrict__ targets) {
    const int bid  = blockIdx.x;
    const int lane = threadIdx.x & 31;

    if ((bid & 3) == 3) {
        // ---------------- MATCH PART (bid -> 0..959) ----------------
        const int mb    = bid >> 2;
        const int gwarp = mb * 8 + (threadIdx.x >> 5);       // 0..7679
        const int chunk = gwarp % MCHUNKS;
        const int btg   = gwarp / MCHUNKS;                   // 0..159
        const int tg    = btg % NTG;
        const int b     = btg / NTG;

        float tx0[TG], ty0[TG], tx1[TG], ty1[TG], ta[TG];
        const float* tbase = targets + (size_t)(b * NT + tg * TG) * 5;
        #pragma unroll
        for (int j = 0; j < TG; j++) {
            tx0[j] = tbase[j * 5 + 0]; ty0[j] = tbase[j * 5 + 1];
            tx1[j] = tbase[j * 5 + 2]; ty1[j] = tbase[j * 5 + 3];
            ta[j]  = (tx1[j] - tx0[j]) * (ty1[j] - ty0[j]);
        }

        const int pend = min(NP, (chunk + 1) * MCHUNK);
        float bestOv[TG];
        int   bestP[TG];
        #pragma unroll
        for (int j = 0; j < TG; j++) { bestOv[j] = 0.0f; bestP[j] = 0; }

        #pragma unroll 4
        for (int p = chunk * MCHUNK + lane; p < pend; p += 32) {
            const float4 pr = reinterpret_cast<const float4*>(priors)[p];
            const float hz = 0.5f * pr.z, hw = 0.5f * pr.w;
            const float px0 = pr.x - hz, px1 = pr.x + hz;
            const float py0 = pr.y - hw, py1 = pr.y + hw;
            const float pa  = pr.z * pr.w;
            #pragma unroll
            for (int j = 0; j < TG; j++) {
                const float iw = fmaxf(fminf(tx1[j], px1) - fmaxf(tx0[j], px0), 0.0f);
                const float ih = fmaxf(fminf(ty1[j], py1) - fmaxf(ty0[j], py0), 0.0f);
                const float inter = iw * ih;
                const float ov = __fdividef(inter, ta[j] + pa - inter);
                if (ov > bestOv[j]) { bestOv[j] = ov; bestP[j] = p; } // smallest p in-lane
            }
        }

        #pragma unroll
        for (int j = 0; j < TG; j++) {
            unsigned long long key =
                ((unsigned long long)__float_as_uint(bestOv[j]) << 32) |
                (unsigned int)(~(unsigned int)bestP[j]);
            #pragma unroll
            for (int o = 16; o; o >>= 1) {
                unsigned long long other = __shfl_xor_sync(0xffffffffu, key, o);
                key = (other > key) ? other : key;
            }
            if (lane == 0) atomicMax(&g_keys[b * NT + tg * TG + j], key);
        }
    } else {
        // ---------------- LSE PART (bid -> 0..2879) ----------------
        // Unshifted logsumexp (logits ~N(0,1) -> fp32-safe). 16-lane half owns
        // one row; 2 row-pairs per iteration; stores {sum(exp), logit[0]} per row.
        const int lb   = bid - (bid >> 2);     // lse block index 0..G1_LSE-1
        const int hl   = lane & 15;
        const int h    = lane >> 4;
        const int gw   = lb * 8 + (threadIdx.x >> 5);
        const int nW   = NW_LSE;

        const size_t rstride = (size_t)nW * 2 * NC;
        const float* rpA = conf + (size_t)(2 * gw + h) * NC;

        int r2 = gw;
        for (; r2 + nW < TOT2; r2 += 2 * nW, rpA += 2 * rstride) {
            const float* rpB = rpA + rstride;
            const float* crA = rpA + hl;
            const float* crB = rpB + hl;

            const float a0 = __ldcs(crA),      b0 = __ldcs(crB);
            const float a1 = __ldcs(crA + 16), b1 = __ldcs(crB + 16);
            const float a2 = __ldcs(crA + 32), b2 = __ldcs(crB + 32);
            const float a3 = __ldcs(crA + 48), b3 = __ldcs(crB + 48);
            const float a4 = __ldcs(crA + 64), b4 = __ldcs(crB + 64);
            const float a5 = (hl == 0) ? __ldcs(crA + 80) : -INFINITY;
            const float b5 = (hl == 0) ? __ldcs(crB + 80) : -INFINITY;

            float eA = __expf(a0) + __expf(a1) + __expf(a2) +
                       __expf(a3) + __expf(a4) + __expf(a5);
            float eB = __expf(b0) + __expf(b1) + __expf(b2) +
                       __expf(b3) + __expf(b4) + __expf(b5);
            #pragma unroll
            for (int o = 8; o; o >>= 1) {
                eA += __shfl_xor_sync(0xffffffffu, eA, o);
                eB += __shfl_xor_sync(0xffffffffu, eB, o);
            }
            if (hl == 0) {                       // lanes 0 and 16: a0/b0 ARE logit[0]
                g_lse2[2 * r2 + h] = make_float2(eA, a0);
                g_lse2[2 * (r2 + nW) + h] = make_float2(eB, b0);
            }
        }
        for (; r2 < TOT2; r2 += nW, rpA += rstride) {
            const float* cr = rpA + hl;
            const float c0 = __ldcs(cr);
            const float c1 = __ldcs(cr + 16);
            const float c2 = __ldcs(cr + 32);
            const float c3 = __ldcs(cr + 48);
            const float c4 = __ldcs(cr + 64);
            const float c5 = (hl == 0) ? __ldcs(cr + 80) : -INFINITY;
            float e = __expf(c0) + __expf(c1) + __expf(c2) +
                      __expf(c3) + __expf(c4) + __expf(c5);
            #pragma unroll
            for (int o = 8; o; o >>= 1) e += __shfl_xor_sync(0xffffffffu, e, o);
            if (hl == 0) g_lse2[2 * r2 + h] = make_float2(e, c0);
        }
    }
}

// =====================================================================
// Launch 2: thread-per-row decode + smooth-L1 + focal tail + finalize
// =====================================================================
__device__ __forceinline__ float sl1f(float d) {
    float a = fabsf(d);
    return (a < 1.0f) ? 0.5f * d * d : a - 0.5f;
}

__global__ void __launch_bounds__(256) k_tail(const float* __restrict__ loc,
                                              const float* __restrict__ conf,
                                              const float* __restrict__ priors,
                                              const float* __restrict__ targets,
                                              float* __restrict__ out) {
    __shared__ float4 s_box[NB * NT];    // x0, y0, x1, y1
    __shared__ float4 s_meta[NB * NT];   // ta, label, bp-bits, unused
    __shared__ double sL[8], sC[8], sN[8];
    __shared__ int sLast;

    for (int i = threadIdx.x; i < NB * NT; i += blockDim.x) {
        const float* tg = targets + (size_t)i * 5;
        const float x0 = tg[0], y0 = tg[1], x1 = tg[2], y1 = tg[3];
        s_box[i] = make_float4(x0, y0, x1, y1);
        const int bp = (int)(~(unsigned int)(g_keys[i] & 0xffffffffull));
        s_meta[i] = make_float4((x1 - x0) * (y1 - y0), tg[4], __int_as_float(bp), 0.0f);
    }
    __syncthreads();

    const int row = blockIdx.x * 256 + threadIdx.x;
    double myL = 0.0, myC = 0.0, myN = 0.0;

    if (row < TOT) {
        const int b = row / NP;
        const int p = row - b * NP;
        const int base = b * NT;

        const float4 pr = reinterpret_cast<const float4*>(priors)[p];
        const float px0 = pr.x - 0.5f * pr.z, py0 = pr.y - 0.5f * pr.w;
        const float px1 = pr.x + 0.5f * pr.z, py1 = pr.y + 0.5f * pr.w;
        const float parea = pr.z * pr.w;

        float bestOv = -1.0f;
        int bestT = 0, forcedT = -1;
        #pragma unroll
        for (int t = 0; t < NT; t++) {
            const float4 bx = s_box[base + t];
            const float4 mt = s_meta[base + t];
            float iw = fmaxf(fminf(bx.z, px1) - fmaxf(bx.x, px0), 0.0f);
            float ih = fmaxf(fminf(bx.w, py1) - fmaxf(bx.y, py0), 0.0f);
            float inter = iw * ih;
            float ov = __fdividef(inter, mt.x + parea - inter);
            if (ov > bestOv) { bestOv = ov; bestT = t; }   // tie -> smallest t
            if (__float_as_int(mt.z) == p) forcedT = t;    // ascending -> largest t wins
        }
        if (forcedT >= 0) { bestOv = 2.0f; bestT = forcedT; }

        const int ti = base + bestT;
        const float4 mbox = s_box[ti];
        int cls = (int)s_meta[ti].y + 1;
        if (bestOv < 0.5f) cls = -1;
        if (bestOv < 0.4f) cls = 0;

        // focal tail: {sum(exp), logit0} from scratch; gather only for pos rows
        const float2 lse = g_lse2[row];
        const float lv = (cls > 0) ? __ldg(conf + (size_t)row * NC + cls) : lse.y;
        const float logpt = lv - __logf(lse.x);
        const float pt    = __expf(logpt);
        const float at    = (cls > 0) ? 0.25f : 0.75f;
        const float om    = 1.0f - pt;
        if (cls >= 0) myC = (double)(-at * om * om * logpt);

        if (cls > 0) {
            const float4 ld = reinterpret_cast<const float4*>(loc)[row];
            const float gx = ((mbox.x + mbox.z) * 0.5f - pr.x) / (0.1f * pr.z);
            const float gy = ((mbox.y + mbox.w) * 0.5f - pr.y) / (0.1f * pr.w);
            const float gw2 = __logf((mbox.z - mbox.x) / pr.z) * 5.0f;  // /0.2
            const float gh2 = __logf((mbox.w - mbox.y) / pr.w) * 5.0f;
            myL = (double)(sl1f(ld.x - gx) + sl1f(ld.y - gy) +
                           sl1f(ld.z - gw2) + sl1f(ld.w - gh2));
            myN = 1.0;
        }
    }

    #pragma unroll
    for (int o = 16; o; o >>= 1) {
        myL += __shfl_down_sync(0xffffffffu, myL, o);
        myC += __shfl_down_sync(0xffffffffu, myC, o);
        myN += __shfl_down_sync(0xffffffffu, myN, o);
    }
    const int lane = threadIdx.x & 31, w = threadIdx.x >> 5;
    if (lane == 0) { sL[w] = myL; sC[w] = myC; sN[w] = myN; }
    if (threadIdx.x == 0) sLast = 0;
    __syncthreads();

    if (threadIdx.x == 0) {
        double tL = 0.0, tC = 0.0, tN = 0.0;
        #pragma unroll
        for (int i = 0; i < 8; i++) { tL += sL[i]; tC += sC[i]; tN += sN[i]; }
        if (tL != 0.0 || tN != 0.0) { atomicAdd(&g_accL, tL); atomicAdd(&g_accN, tN); }
        atomicAdd(&g_accC, tC);
        __threadfence();
        const unsigned my = atomicAdd(&g_ticket, 1u);
        if (my == G2 - 1) sLast = 1;
    }
    __syncthreads();

    if (sLast) {
        // all other blocks fully done (ticket): safe to reset scratch for replay
        for (int i = threadIdx.x; i < NB * NT; i += 256) g_keys[i] = 0ull;
        if (threadIdx.x == 0) {
            const double L = *(volatile double*)&g_accL;
            const double C = *(volatile double*)&g_accC;
            const double N = *(volatile double*)&g_accN;
            out[0] = (float)(L / N);
            out[1] = (float)(C / N);
            *(volatile double*)&g_accL = 0.0;
            *(volatile double*)&g_accC = 0.0;
            *(volatile double*)&g_accN = 0.0;
            *(volatile unsigned int*)&g_ticket = 0u;
        }
    }
}

// ---------------- launch ----------------
extern "C" void kernel_launch(void* const* d_in, const int* in_sizes, int n_in,
                              void* d_out, int out_size) {
    const float* loc     = (const float*)d_in[0];
    const float* conf    = (const float*)d_in[1];
    const float* priors  = (const float*)d_in[2];
    const float* targets = (const float*)d_in[3];
    float* out = (float*)d_out;

    k_stream<<<G1_TOT, 256>>>(conf, priors, targets);
    k_tail<<<G2, 256>>>(loc, conf, priors, targets, out);
}